// round 4
// baseline (speedup 1.0000x reference)
#include <cuda_runtime.h>
#include <math.h>

// ---------------- static workspace (no allocations allowed) ----------------
#define CHUNKS 256
__device__ float g_x0[25165824];   // max N*Bt*Fin = 768*256*128
__device__ float g_x1[25165824];
__device__ float g_x2[25165824];
__device__ float g_y [12582912];   // max conv output = 768*256*64
__device__ float g_s3[12582912];   // 768*256*64
__device__ float g_s2[ 6291456];   // 192*256*128
__device__ float g_s1[ 3145728];   // 48*256*256
__device__ float g_part[CHUNKS * 512];
__device__ float g_bnp[512];       // [0..F) scale, [F..2F) shift

// ---------------- generic SGEMM: C = alpha * A@B + beta * D ----------------
// A: MxK row-major, B: KxN row-major, C/D: MxN row-major. D may be null (beta=0)
#define BM 128
#define BN 128
#define BKK 8

__global__ __launch_bounds__(256) void sgemm_k(
    const float* __restrict__ A, const float* __restrict__ B,
    const float* __restrict__ D, float* __restrict__ C,
    int M, int N, int K, float alpha, float beta)
{
    __shared__ float As[BKK][BM + 4];   // transposed A tile, padded
    __shared__ float Bs[BKK][BN];

    int tid = threadIdx.x;
    int tx = tid & 15, ty = tid >> 4;
    int m0 = blockIdx.y * BM, n0 = blockIdx.x * BN;

    float acc[8][8];
#pragma unroll
    for (int i = 0; i < 8; i++)
#pragma unroll
        for (int j = 0; j < 8; j++) acc[i][j] = 0.0f;

    int arow = tid >> 1;          // 0..127
    int acol = (tid & 1) * 4;     // 0 or 4
    int brow = tid >> 5;          // 0..7
    int bcol = (tid & 31) * 4;    // 0..124

    for (int k0 = 0; k0 < K; k0 += BKK) {
        // --- load A tile (transposed into smem) ---
        float4 av = make_float4(0.f, 0.f, 0.f, 0.f);
        int ga_r = m0 + arow;
        int ga_c = k0 + acol;
        if (ga_r < M) {
            const float* p = A + (size_t)ga_r * K;
            if (ga_c + 3 < K) {
                av = *(const float4*)(p + ga_c);
            } else {
                if (ga_c + 0 < K) av.x = p[ga_c + 0];
                if (ga_c + 1 < K) av.y = p[ga_c + 1];
                if (ga_c + 2 < K) av.z = p[ga_c + 2];
                if (ga_c + 3 < K) av.w = p[ga_c + 3];
            }
        }
        As[acol + 0][arow] = av.x;
        As[acol + 1][arow] = av.y;
        As[acol + 2][arow] = av.z;
        As[acol + 3][arow] = av.w;

        // --- load B tile ---
        float4 bv = make_float4(0.f, 0.f, 0.f, 0.f);
        int gb_r = k0 + brow;
        int gb_c = n0 + bcol;
        if (gb_r < K) {
            const float* p = B + (size_t)gb_r * N;
            if (gb_c + 3 < N) {
                bv = *(const float4*)(p + gb_c);
            } else {
                if (gb_c + 0 < N) bv.x = p[gb_c + 0];
                if (gb_c + 1 < N) bv.y = p[gb_c + 1];
                if (gb_c + 2 < N) bv.z = p[gb_c + 2];
                if (gb_c + 3 < N) bv.w = p[gb_c + 3];
            }
        }
        *(float4*)&Bs[brow][bcol] = bv;
        __syncthreads();

#pragma unroll
        for (int kk = 0; kk < BKK; kk++) {
            float a[8], b[8];
            *(float4*)&a[0] = *(const float4*)&As[kk][ty * 8];
            *(float4*)&a[4] = *(const float4*)&As[kk][ty * 8 + 4];
            *(float4*)&b[0] = *(const float4*)&Bs[kk][tx * 8];
            *(float4*)&b[4] = *(const float4*)&Bs[kk][tx * 8 + 4];
#pragma unroll
            for (int i = 0; i < 8; i++)
#pragma unroll
                for (int j = 0; j < 8; j++) acc[i][j] += a[i] * b[j];
        }
        __syncthreads();
    }

    // --- epilogue ---
#pragma unroll
    for (int i = 0; i < 8; i++) {
        int r = m0 + ty * 8 + i;
        if (r < M) {
            size_t ro = (size_t)r * N;
#pragma unroll
            for (int j = 0; j < 8; j++) {
                int c = n0 + tx * 8 + j;
                if (c < N) {
                    float v = alpha * acc[i][j];
                    if (beta != 0.0f) v += beta * D[ro + c];
                    C[ro + c] = v;
                }
            }
        }
    }
}

// ---------------- elementwise / reduction kernels ----------------

// dst[(n*256+bt)*8+c] = x[b,c,hw,n] with bt = b*64+hw ; x: (4,8,64,768)
__global__ __launch_bounds__(256) void k_transpose_in(const float* __restrict__ x,
                                                      float* __restrict__ dst, int total)
{
    int i = blockIdx.x * blockDim.x + threadIdx.x;
    if (i >= total) return;
    int c  = i & 7;
    int bt = (i >> 3) & 255;
    int n  = i >> 11;
    int b  = bt >> 6, hw = bt & 63;
    dst[i] = x[(((b << 3) + c) * 64 + hw) * 768 + n];
}

// per-chunk partial sums/sumsqs per channel (deterministic)
__global__ __launch_bounds__(256) void k_bn_partial(const float* __restrict__ Y,
                                                    int rows, int F, float* __restrict__ part)
{
    __shared__ float sh[512];
    int blk = blockIdx.x;
    int rpc = (rows + CHUNKS - 1) / CHUNKS;
    int r0 = blk * rpc;
    int r1 = rows < r0 + rpc ? rows : r0 + rpc;
    int tid = threadIdx.x;
    int c = tid % F;
    int g = tid / F;
    int GP = blockDim.x / F;
    float s = 0.f, q = 0.f;
    for (int r = r0 + g; r < r1; r += GP) {
        float v = Y[(size_t)r * F + c];
        s += v; q += v * v;
    }
    sh[tid] = s;
    sh[256 + tid] = q;
    __syncthreads();
    if (g == 0) {
        for (int gg = 1; gg < GP; gg++) {
            s += sh[gg * F + c];
            q += sh[256 + gg * F + c];
        }
        part[blk * 2 * F + c] = s;
        part[blk * 2 * F + F + c] = q;
    }
}

__global__ __launch_bounds__(256) void k_bn_final(const float* __restrict__ part, int F, float cnt,
                                                  const float* __restrict__ gam,
                                                  const float* __restrict__ bet,
                                                  float* __restrict__ bn)
{
    int c = threadIdx.x;
    if (c >= F) return;
    float s = 0.f, q = 0.f;
    for (int ch = 0; ch < CHUNKS; ch++) {
        s += part[ch * 2 * F + c];
        q += part[ch * 2 * F + F + c];
    }
    float mean = s / cnt;
    float var = q / cnt - mean * mean;
    float sc = gam[c] * rsqrtf(var + 1e-5f);
    bn[c] = sc;
    bn[F + c] = bet[c] - mean * sc;
}

__global__ __launch_bounds__(256) void k_bn_apply(const float* __restrict__ Y,
                                                  const float* __restrict__ bn,
                                                  float* __restrict__ dst, int total, int F)
{
    int i = blockIdx.x * blockDim.x + threadIdx.x;
    if (i >= total) return;
    int c = i % F;
    float v = Y[i] * bn[c] + bn[F + c];
    dst[i] = v > 0.f ? v : 0.f;
}

// bn + relu + 4:1 max-pool over node dim (node-major layout)
__global__ __launch_bounds__(256) void k_bn_pool(const float* __restrict__ Y,
                                                 const float* __restrict__ bn,
                                                 float* __restrict__ dst,
                                                 int total /*Nout*Bt*F*/, int F, int BtF)
{
    int i = blockIdx.x * blockDim.x + threadIdx.x;
    if (i >= total) return;
    int c = i % F;
    int inner = i % BtF;
    int j = i / BtF;
    float sc = bn[c], sh = bn[F + c];
    size_t base = (size_t)(4 * j) * BtF + inner;
    float m = Y[base] * sc + sh;
#pragma unroll
    for (int q = 1; q < 4; q++) {
        float v = Y[base + (size_t)q * BtF] * sc + sh;
        if (v > m) m = v;
    }
    dst[i] = m > 0.f ? m : 0.f;
}

// bn + relu + 1:4 unpool, written into concat buffer columns [0, F1)
__global__ __launch_bounds__(256) void k_bn_unpool_cat(const float* __restrict__ Y,
                                                       const float* __restrict__ bn,
                                                       float* __restrict__ dst,
                                                       int total /*N*Bt*F1*/, int F1, int Ftot, int Bt)
{
    int i = blockIdx.x * blockDim.x + threadIdx.x;
    if (i >= total) return;
    int f = i % F1;
    int r = i / F1;          // r = n*Bt + bt
    int bt = r % Bt;
    int n = r / Bt;
    int j = n >> 2;
    float v = Y[((size_t)j * Bt + bt) * F1 + f] * bn[f] + bn[F1 + f];
    dst[(size_t)r * Ftot + f] = v > 0.f ? v : 0.f;
}

// copy skip into concat buffer columns [off, off+Fs)
__global__ __launch_bounds__(256) void k_copy_cat(const float* __restrict__ S,
                                                  float* __restrict__ dst,
                                                  int total /*rows*Fs*/, int Fs, int Ftot, int off)
{
    int i = blockIdx.x * blockDim.x + threadIdx.x;
    if (i >= total) return;
    int f = i % Fs;
    int r = i / Fs;
    dst[(size_t)r * Ftot + off + f] = S[i];
}

// out[bt*768 + n] = Y[n*256 + bt]
__global__ __launch_bounds__(256) void k_transpose_out(const float* __restrict__ Y,
                                                       float* __restrict__ out)
{
    int i = blockIdx.x * blockDim.x + threadIdx.x;
    if (i >= 196608) return;
    int n = i % 768, bt = i / 768;
    out[i] = Y[n * 256 + bt];
}

// ---------------- host orchestration ----------------
static inline void gemm(const float* A, const float* B, const float* D, float* C,
                        int M, int N, int K, float alpha, float beta)
{
    dim3 grid((N + BN - 1) / BN, (M + BM - 1) / BM);
    sgemm_k<<<grid, 256>>>(A, B, D, C, M, N, K, alpha, beta);
}

extern "C" void kernel_launch(void* const* d_in, const int* in_sizes, int n_in,
                              void* d_out, int out_size)
{
    const float* x    = (const float*)d_in[0];
    const float* L3   = (const float*)d_in[1];
    const float* L2   = (const float*)d_in[2];
    const float* L1   = (const float*)d_in[3];
    const float* L0   = (const float*)d_in[4];
    const float* w_e3a = (const float*)d_in[5];
    const float* g_e3a = (const float*)d_in[6];
    const float* b_e3a = (const float*)d_in[7];
    const float* w_e3b = (const float*)d_in[8];
    const float* g_e3b = (const float*)d_in[9];
    const float* b_e3b = (const float*)d_in[10];
    const float* w_e2  = (const float*)d_in[11];
    const float* g_e2  = (const float*)d_in[12];
    const float* b_e2  = (const float*)d_in[13];
    const float* w_e1  = (const float*)d_in[14];
    const float* g_e1  = (const float*)d_in[15];
    const float* b_e1  = (const float*)d_in[16];
    const float* w_e0  = (const float*)d_in[17];
    const float* g_e0  = (const float*)d_in[18];
    const float* b_e0  = (const float*)d_in[19];
    const float* w_d1  = (const float*)d_in[20];
    const float* g_d1  = (const float*)d_in[21];
    const float* b_d1  = (const float*)d_in[22];
    const float* w_d2  = (const float*)d_in[23];
    const float* g_d2  = (const float*)d_in[24];
    const float* b_d2  = (const float*)d_in[25];
    const float* w_d3  = (const float*)d_in[26];
    const float* g_d3  = (const float*)d_in[27];
    const float* b_d3  = (const float*)d_in[28];
    const float* w_out = (const float*)d_in[29];
    float* out = (float*)d_out;

    float *X0, *X1, *X2, *Yb, *S3, *S2, *S1, *Pt, *BNp;
    cudaGetSymbolAddress((void**)&X0, g_x0);
    cudaGetSymbolAddress((void**)&X1, g_x1);
    cudaGetSymbolAddress((void**)&X2, g_x2);
    cudaGetSymbolAddress((void**)&Yb, g_y);
    cudaGetSymbolAddress((void**)&S3, g_s3);
    cudaGetSymbolAddress((void**)&S2, g_s2);
    cudaGetSymbolAddress((void**)&S1, g_s1);
    cudaGetSymbolAddress((void**)&Pt, g_part);
    cudaGetSymbolAddress((void**)&BNp, g_bnp);

    const int Bt = 256;

    auto cheb = [&](const float* L, int Nn, int Fin, int Fout, const float* w) {
        int rows = Nn * Bt;
        int cols = Bt * Fin;
        // Y = X0 @ w0
        gemm(X0, w, nullptr, Yb, rows, Fout, Fin, 1.f, 0.f);
        // X1 = L @ X0
        gemm(L, X0, nullptr, X1, Nn, cols, Nn, 1.f, 0.f);
        // Y += X1 @ w1
        gemm(X1, w + (size_t)Fin * Fout, Yb, Yb, rows, Fout, Fin, 1.f, 1.f);
        // X2 = 2 L @ X1 - X0
        gemm(L, X1, X0, X2, Nn, cols, Nn, 2.f, -1.f);
        // Y += X2 @ w2
        gemm(X2, w + 2 * (size_t)Fin * Fout, Yb, Yb, rows, Fout, Fin, 1.f, 1.f);
        // X3 = 2 L @ X2 - X1  (into X0)
        gemm(L, X2, X1, X0, Nn, cols, Nn, 2.f, -1.f);
        // Y += X3 @ w3
        gemm(X0, w + 3 * (size_t)Fin * Fout, Yb, Yb, rows, Fout, Fin, 1.f, 1.f);
    };

    auto stats = [&](int rows, int F, const float* gam, const float* bet) {
        k_bn_partial<<<CHUNKS, 256>>>(Yb, rows, F, Pt);
        k_bn_final<<<1, 256>>>(Pt, F, (float)rows, gam, bet, BNp);
    };
    auto elgrid = [](int total) { return (total + 255) / 256; };

    // ---- input transpose: (4,8,8,8,768) -> node-major (768,256,8) ----
    {
        int total = 768 * Bt * 8;
        k_transpose_in<<<elgrid(total), 256>>>(x, X0, total);
    }

    // ---- e3a: L3, 8 -> 32 ----
    cheb(L3, 768, 8, 32, w_e3a);
    stats(768 * Bt, 32, g_e3a, b_e3a);
    k_bn_apply<<<elgrid(768 * Bt * 32), 256>>>(Yb, BNp, X0, 768 * Bt * 32, 32);

    // ---- e3b: L3, 32 -> 64 ; s3 skip + pool ----
    cheb(L3, 768, 32, 64, w_e3b);
    stats(768 * Bt, 64, g_e3b, b_e3b);
    k_bn_apply<<<elgrid(768 * Bt * 64), 256>>>(Yb, BNp, S3, 768 * Bt * 64, 64);
    k_bn_pool<<<elgrid(192 * Bt * 64), 256>>>(Yb, BNp, X0, 192 * Bt * 64, 64, Bt * 64);

    // ---- e2: L2, 64 -> 128 ; s2 skip + pool ----
    cheb(L2, 192, 64, 128, w_e2);
    stats(192 * Bt, 128, g_e2, b_e2);
    k_bn_apply<<<elgrid(192 * Bt * 128), 256>>>(Yb, BNp, S2, 192 * Bt * 128, 128);
    k_bn_pool<<<elgrid(48 * Bt * 128), 256>>>(Yb, BNp, X0, 48 * Bt * 128, 128, Bt * 128);

    // ---- e1: L1, 128 -> 256 ; s1 skip + pool ----
    cheb(L1, 48, 128, 256, w_e1);
    stats(48 * Bt, 256, g_e1, b_e1);
    k_bn_apply<<<elgrid(48 * Bt * 256), 256>>>(Yb, BNp, S1, 48 * Bt * 256, 256);
    k_bn_pool<<<elgrid(12 * Bt * 256), 256>>>(Yb, BNp, X0, 12 * Bt * 256, 256, Bt * 256);

    // ---- e0: L0, 256 -> 256 ----
    cheb(L0, 12, 256, 256, w_e0);
    stats(12 * Bt, 256, g_e0, b_e0);
    // unpool(bn(h)) -> X0 cols [0,256), skip s1 -> cols [256,512), Ftot=512
    k_bn_unpool_cat<<<elgrid(48 * Bt * 256), 256>>>(Yb, BNp, X0, 48 * Bt * 256, 256, 512, Bt);
    k_copy_cat<<<elgrid(48 * Bt * 256), 256>>>(S1, X0, 48 * Bt * 256, 256, 512, 256);

    // ---- d1: L1, 512 -> 128 ----
    cheb(L1, 48, 512, 128, w_d1);
    stats(48 * Bt, 128, g_d1, b_d1);
    k_bn_unpool_cat<<<elgrid(192 * Bt * 128), 256>>>(Yb, BNp, X0, 192 * Bt * 128, 128, 256, Bt);
    k_copy_cat<<<elgrid(192 * Bt * 128), 256>>>(S2, X0, 192 * Bt * 128, 128, 256, 128);

    // ---- d2: L2, 256 -> 64 ----
    cheb(L2, 192, 256, 64, w_d2);
    stats(192 * Bt, 64, g_d2, b_d2);
    k_bn_unpool_cat<<<elgrid(768 * Bt * 64), 256>>>(Yb, BNp, X0, 768 * Bt * 64, 64, 128, Bt);
    k_copy_cat<<<elgrid(768 * Bt * 64), 256>>>(S3, X0, 768 * Bt * 64, 64, 128, 64);

    // ---- d3: L3, 128 -> 32 ----
    cheb(L3, 768, 128, 32, w_d3);
    stats(768 * Bt, 32, g_d3, b_d3);
    k_bn_apply<<<elgrid(768 * Bt * 32), 256>>>(Yb, BNp, X0, 768 * Bt * 32, 32);

    // ---- out: L3, 32 -> 1 (no BN) ----
    cheb(L3, 768, 32, 1, w_out);

    // ---- output transpose -> (4,1,8,8,768) ----
    k_transpose_out<<<elgrid(196608), 256>>>(Yb, out);
}